// round 13
// baseline (speedup 1.0000x reference)
#include <cuda_runtime.h>
#include <cuda_fp16.h>
#include <cstdint>
#include <cstddef>

// ---------------------------------------------------------------------------
// Problem constants
// ---------------------------------------------------------------------------
#define B_  512
#define L_  64
#define H_  512
#define G3  1536            // 3*H
#define XW  575             // T + L - 1
#define KP  1024            // expanded K: [hi(512) | lo(512)] (fp16 split, A side)
#define BM  128
#define BN  128
#define BKC 64              // fp16 K per chunk
#define NCH (KP / BKC)      // 16
#define APAD_B 144          // padded smem row stride in bytes (64*2 + 16)
#define TILE_BYTES (BM * APAD_B)        // 18432
#define SMEM_P1   (4 * TILE_BYTES)      // 2-stage x (A,W) = 73728
#define SMEM_STEP (8 * TILE_BYTES)      // 4-stage x (A,W) = 147456

// ---------------------------------------------------------------------------
// Scratch (device globals; allocation is forbidden)
// ---------------------------------------------------------------------------
__device__ __align__(16) float g_GI1[(size_t)L_ * B_ * G3];
__device__ __align__(16) float g_GH1[B_ * G3];
__device__ __align__(16) float g_GI2[B_ * G3];
__device__ __align__(16) float g_GH2[B_ * G3];
__device__ __align__(16) float g_h1[B_ * H_];
__device__ __align__(16) float g_h2[B_ * H_];
__device__ __align__(16) float g_h2hist[(size_t)L_ * B_ * H_];   // h2 after each step

__device__ __align__(16) __half g_h1e[B_ * KP];                // [hi|lo]
__device__ __align__(16) __half g_h2e[B_ * KP];
__device__ __align__(16) __half g_Axp[(size_t)L_ * B_ * KP];   // x windows [hi|lo]
__device__ __align__(16) __half g_Wih1e[(size_t)G3 * KP];      // [Whi|Whi]
__device__ __align__(16) __half g_Whh1e[(size_t)G3 * KP];
__device__ __align__(16) __half g_Wih2e[(size_t)G3 * KP];
__device__ __align__(16) __half g_Whh2e[(size_t)G3 * KP];

// ---------------------------------------------------------------------------
// Helpers
// ---------------------------------------------------------------------------
__device__ __forceinline__ uint32_t s2u(const void* p) {
    return (uint32_t)__cvta_generic_to_shared(p);
}
__device__ __forceinline__ void cpa16(uint32_t dst, const void* src) {
    asm volatile("cp.async.cg.shared.global [%0], [%1], 16;" :: "r"(dst), "l"(src));
}
__device__ __forceinline__ void cpa_commit() {
    asm volatile("cp.async.commit_group;" ::: "memory");
}
template <int N> __device__ __forceinline__ void cpa_wait() {
    asm volatile("cp.async.wait_group %0;" :: "n"(N) : "memory");
}
__device__ __forceinline__ void ldsm4(uint32_t& r0, uint32_t& r1, uint32_t& r2,
                                      uint32_t& r3, uint32_t addr) {
    asm volatile("ldmatrix.sync.aligned.m8n8.x4.shared.b16 {%0,%1,%2,%3}, [%4];"
                 : "=r"(r0), "=r"(r1), "=r"(r2), "=r"(r3) : "r"(addr));
}
__device__ __forceinline__ void mma16816(float* d, const uint32_t* a,
                                         uint32_t b0, uint32_t b1) {
    asm volatile(
        "mma.sync.aligned.m16n8k16.row.col.f32.f16.f16.f32 "
        "{%0,%1,%2,%3}, {%4,%5,%6,%7}, {%8,%9}, {%0,%1,%2,%3};"
        : "+f"(d[0]), "+f"(d[1]), "+f"(d[2]), "+f"(d[3])
        : "r"(a[0]), "r"(a[1]), "r"(a[2]), "r"(a[3]), "r"(b0), "r"(b1));
}
__device__ __forceinline__ float sigf(float v) { return 1.f / (1.f + __expf(-v)); }

// ---------------------------------------------------------------------------
// Chunk loader: A tile [128 x 64] + W tile [128 x 64] fp16, 144B-padded rows.
// ---------------------------------------------------------------------------
__device__ __forceinline__ void load_tile(const __half* __restrict__ A,
                                          const __half* __restrict__ W,
                                          int m0, int n0, int kc,
                                          uint32_t sA, uint32_t sW, int tid)
{
#pragma unroll
    for (int i = 0; i < 4; i++) {
        const int g  = tid + i * 256;   // 0..1023
        const int r  = g >> 3;          // row 0..127
        const int cg = g & 7;           // 16B granule in row
        const uint32_t so = (uint32_t)(r * APAD_B + cg * 16);
        cpa16(sA + so, A + (size_t)(m0 + r) * KP + kc * BKC + cg * 8);
        cpa16(sW + so, W + (size_t)(n0 + r) * KP + kc * BKC + cg * 8);
    }
    cpa_commit();
}

// ---------------------------------------------------------------------------
// GEMM core: C[m0:+128, n0:+128] = A @ W^T + bias. NSTAGE-deep cp.async
// pipeline (NSTAGE must be a power of two), 256 threads.
// ---------------------------------------------------------------------------
template <int NSTAGE>
__device__ __forceinline__ void gemm_core(const __half* __restrict__ A,
                                          const __half* __restrict__ W,
                                          const float* __restrict__ bias,
                                          float* __restrict__ C,
                                          int m0, int n0, char* smem, int tid)
{
    const int warp = tid >> 5;
    const int lane = tid & 31;
    const int wm   = warp >> 2;        // 0..1
    const int wn   = warp & 3;         // 0..3

    const uint32_t sb = s2u(smem);

    const uint32_t aoff = (uint32_t)((wm * 64 + (lane & 15)) * APAD_B + (lane >> 4) * 16);
    const int bg = lane >> 3;
    const uint32_t boff = (uint32_t)((wn * 32 + ((bg >> 1) * 8) + (lane & 7)) * APAD_B
                                     + (bg & 1) * 16);

    float acc[4][4][4];
#pragma unroll
    for (int i = 0; i < 4; i++)
#pragma unroll
        for (int j = 0; j < 4; j++)
#pragma unroll
            for (int e = 0; e < 4; e++) acc[i][j][e] = 0.f;

    // Prologue: fill NSTAGE-1 stages
#pragma unroll
    for (int s = 0; s < NSTAGE - 1; s++) {
        const uint32_t base = sb + (uint32_t)(s * 2 * TILE_BYTES);
        load_tile(A, W, m0, n0, s, base, base + TILE_BYTES, tid);
    }

#pragma unroll 1
    for (int c = 0; c < NCH; c++) {
        __syncthreads();               // stage (c-1)&mask fully consumed before reuse
        if (c + NSTAGE - 1 < NCH) {
            const int s = (c + NSTAGE - 1) & (NSTAGE - 1);
            const uint32_t base = sb + (uint32_t)(s * 2 * TILE_BYTES);
            load_tile(A, W, m0, n0, c + NSTAGE - 1, base, base + TILE_BYTES, tid);
        } else {
            cpa_commit();              // keep group count uniform
        }
        cpa_wait<NSTAGE - 1>();        // chunk c complete
        __syncthreads();

        const uint32_t base = sb + (uint32_t)((c & (NSTAGE - 1)) * 2 * TILE_BYTES);
        const uint32_t bufA = base;
        const uint32_t bufW = base + TILE_BYTES;

#pragma unroll
        for (int ks = 0; ks < 4; ks++) {
            uint32_t a[4][4];
            uint32_t b[8];
#pragma unroll
            for (int mi = 0; mi < 4; mi++)
                ldsm4(a[mi][0], a[mi][1], a[mi][2], a[mi][3],
                      bufA + aoff + mi * (16 * APAD_B) + ks * 32);
            ldsm4(b[0], b[1], b[2], b[3], bufW + boff + ks * 32);
            ldsm4(b[4], b[5], b[6], b[7], bufW + boff + 16 * APAD_B + ks * 32);
#pragma unroll
            for (int mi = 0; mi < 4; mi++)
#pragma unroll
                for (int nj = 0; nj < 4; nj++)
                    mma16816(acc[mi][nj], a[mi], b[nj * 2], b[nj * 2 + 1]);
        }
    }

    // Epilogue: fused bias, direct fp32 stores
    const int r    = lane >> 2;
    const int cpos = (lane & 3) * 2;
#pragma unroll
    for (int mi = 0; mi < 4; mi++) {
        const int m = m0 + wm * 64 + mi * 16 + r;
        float* row0 = C + (size_t)m * G3;
        float* row1 = C + (size_t)(m + 8) * G3;
#pragma unroll
        for (int nj = 0; nj < 4; nj++) {
            const int n = n0 + wn * 32 + nj * 8 + cpos;
            const float bx = bias[n];
            const float by = bias[n + 1];
            *reinterpret_cast<float2*>(row0 + n) =
                make_float2(acc[mi][nj][0] + bx, acc[mi][nj][1] + by);
            *reinterpret_cast<float2*>(row1 + n) =
                make_float2(acc[mi][nj][2] + bx, acc[mi][nj][3] + by);
        }
    }
}

// ---------------------------------------------------------------------------
// Phase-1 kernel: grid (12, 260). y<256: GI1 tiles; y>=256: initial GH1 tiles.
// 2-stage, occupancy 2.
// ---------------------------------------------------------------------------
__global__ void __launch_bounds__(256, 2) gemm_phase1(const float* __restrict__ b_ih1,
                                                      const float* __restrict__ b_hh1)
{
    extern __shared__ __align__(128) char smem[];
    const int by = blockIdx.y;
    if (by < 256) {
        gemm_core<2>(g_Axp, g_Wih1e, b_ih1, g_GI1,
                     by * BM, blockIdx.x * BN, smem, threadIdx.x);
    } else {
        gemm_core<2>(g_h1e, g_Whh1e, b_hh1, g_GH1,
                     (by - 256) * BM, blockIdx.x * BN, smem, threadIdx.x);
    }
}

// ---------------------------------------------------------------------------
// Per-step 3-way GEMM: grid (12, 4, 3). 4-stage pipeline (occ 1, deep prefetch).
// ---------------------------------------------------------------------------
__global__ void __launch_bounds__(256, 1) gemm_step(const float* __restrict__ b_hh1,
                                                    const float* __restrict__ b_ih2,
                                                    const float* __restrict__ b_hh2)
{
    extern __shared__ __align__(128) char smem[];
    const __half* A;
    const __half* W;
    const float* bias;
    float* C;
    switch (blockIdx.z) {
        case 0:  A = g_h1e; W = g_Wih2e; bias = b_ih2; C = g_GI2; break;
        case 1:  A = g_h2e; W = g_Whh2e; bias = b_hh2; C = g_GH2; break;
        default: A = g_h1e; W = g_Whh1e; bias = b_hh1; C = g_GH1; break;
    }
    gemm_core<4>(A, W, bias, C, blockIdx.y * BM, blockIdx.x * BN, smem, threadIdx.x);
}

// ---------------------------------------------------------------------------
// Fused elementwise per step (vectorized x4). CTA b (128 thr, 4 cols/thread):
//   t>0: ew2(t-1) row b  (h2 state + [hi|lo] + history for y)
//   always: ew1(t) row b
// ---------------------------------------------------------------------------
union Pack4 { __half h[4]; uint2 u; };

__global__ void ew_step(int t)
{
    const int b  = blockIdx.x;
    const int j  = threadIdx.x * 4;     // 0..508

    if (t > 0) {
        const float* gi = g_GI2 + (size_t)b * G3;
        const float* gh = g_GH2 + (size_t)b * G3;
        const float4 gir = *reinterpret_cast<const float4*>(gi + j);
        const float4 giz = *reinterpret_cast<const float4*>(gi + H_ + j);
        const float4 gin = *reinterpret_cast<const float4*>(gi + 2 * H_ + j);
        const float4 ghr = *reinterpret_cast<const float4*>(gh + j);
        const float4 ghz = *reinterpret_cast<const float4*>(gh + H_ + j);
        const float4 ghn = *reinterpret_cast<const float4*>(gh + 2 * H_ + j);
        float4 hp = *reinterpret_cast<float4*>(g_h2 + b * H_ + j);

        float hv[4];
        {
            const float gir_[4] = {gir.x, gir.y, gir.z, gir.w};
            const float giz_[4] = {giz.x, giz.y, giz.z, giz.w};
            const float gin_[4] = {gin.x, gin.y, gin.z, gin.w};
            const float ghr_[4] = {ghr.x, ghr.y, ghr.z, ghr.w};
            const float ghz_[4] = {ghz.x, ghz.y, ghz.z, ghz.w};
            const float ghn_[4] = {ghn.x, ghn.y, ghn.z, ghn.w};
            const float hp_[4]  = {hp.x, hp.y, hp.z, hp.w};
#pragma unroll
            for (int e = 0; e < 4; e++) {
                const float r = sigf(gir_[e] + ghr_[e]);
                const float z = sigf(giz_[e] + ghz_[e]);
                const float n = tanhf(gin_[e] + r * ghn_[e]);
                hv[e] = (1.f - z) * n + z * hp_[e];
            }
        }
        const float4 ho = make_float4(hv[0], hv[1], hv[2], hv[3]);
        *reinterpret_cast<float4*>(g_h2 + b * H_ + j) = ho;
        *reinterpret_cast<float4*>(g_h2hist + ((size_t)(t - 1) * B_ + b) * H_ + j) = ho;

        Pack4 phi, plo;
#pragma unroll
        for (int e = 0; e < 4; e++) {
            phi.h[e] = __float2half(hv[e]);
            plo.h[e] = __float2half(hv[e] - __half2float(phi.h[e]));
        }
        *reinterpret_cast<uint2*>(g_h2e + (size_t)b * KP + j)       = phi.u;
        *reinterpret_cast<uint2*>(g_h2e + (size_t)b * KP + 512 + j) = plo.u;
    }

    // ew1(t)
    {
        const float* gi = g_GI1 + ((size_t)t * B_ + b) * G3;
        const float* gh = g_GH1 + (size_t)b * G3;
        const float4 gir = *reinterpret_cast<const float4*>(gi + j);
        const float4 giz = *reinterpret_cast<const float4*>(gi + H_ + j);
        const float4 gin = *reinterpret_cast<const float4*>(gi + 2 * H_ + j);
        const float4 ghr = *reinterpret_cast<const float4*>(gh + j);
        const float4 ghz = *reinterpret_cast<const float4*>(gh + H_ + j);
        const float4 ghn = *reinterpret_cast<const float4*>(gh + 2 * H_ + j);
        float4 hp = *reinterpret_cast<float4*>(g_h1 + b * H_ + j);

        float hv[4];
        {
            const float gir_[4] = {gir.x, gir.y, gir.z, gir.w};
            const float giz_[4] = {giz.x, giz.y, giz.z, giz.w};
            const float gin_[4] = {gin.x, gin.y, gin.z, gin.w};
            const float ghr_[4] = {ghr.x, ghr.y, ghr.z, ghr.w};
            const float ghz_[4] = {ghz.x, ghz.y, ghz.z, ghz.w};
            const float ghn_[4] = {ghn.x, ghn.y, ghn.z, ghn.w};
            const float hp_[4]  = {hp.x, hp.y, hp.z, hp.w};
#pragma unroll
            for (int e = 0; e < 4; e++) {
                const float r = sigf(gir_[e] + ghr_[e]);
                const float z = sigf(giz_[e] + ghz_[e]);
                const float n = tanhf(gin_[e] + r * ghn_[e]);
                hv[e] = (1.f - z) * n + z * hp_[e];
            }
        }
        *reinterpret_cast<float4*>(g_h1 + b * H_ + j) =
            make_float4(hv[0], hv[1], hv[2], hv[3]);

        Pack4 phi, plo;
#pragma unroll
        for (int e = 0; e < 4; e++) {
            phi.h[e] = __float2half(hv[e]);
            plo.h[e] = __float2half(hv[e] - __half2float(phi.h[e]));
        }
        *reinterpret_cast<uint2*>(g_h1e + (size_t)b * KP + j)       = phi.u;
        *reinterpret_cast<uint2*>(g_h1e + (size_t)b * KP + 512 + j) = plo.u;
    }
}

// ---------------------------------------------------------------------------
// Final elementwise: ew2(L-1) + write final h1/h2 + h2hist[L-1].
// ---------------------------------------------------------------------------
__global__ void final_kernel(float* __restrict__ out)
{
    const int b = blockIdx.x;
    const int j = threadIdx.x;
    const float* gi = g_GI2 + (size_t)b * G3;
    const float* gh = g_GH2 + (size_t)b * G3;
    const float r = sigf(gi[j] + gh[j]);
    const float z = sigf(gi[H_ + j] + gh[H_ + j]);
    const float n = tanhf(gi[2 * H_ + j] + r * gh[2 * H_ + j]);
    const float h = (1.f - z) * n + z * g_h2[b * H_ + j];

    g_h2hist[((size_t)(L_ - 1) * B_ + b) * H_ + j] = h;
    out[B_ * L_ + b * H_ + j]           = g_h1[b * H_ + j];   // final h1
    out[B_ * L_ + B_ * H_ + b * H_ + j] = h;                  // final h2
}

// ---------------------------------------------------------------------------
// y_all: ys[b, t] = h2hist[t, b, :] . Wfc + bfc.  grid (L, 64), 256 thr,
// one warp per (t, b).
// ---------------------------------------------------------------------------
__global__ void y_all_kernel(const float* __restrict__ Wfc,
                             const float* __restrict__ bfc,
                             float* __restrict__ ys)
{
    const int t    = blockIdx.x;
    const int b    = blockIdx.y * 8 + (threadIdx.x >> 5);
    const int lane = threadIdx.x & 31;
    const float* hrow = g_h2hist + ((size_t)t * B_ + b) * H_;
    float s = 0.f;
#pragma unroll
    for (int i = 0; i < 4; i++) {
        const int k = i * 128 + lane * 4;
        const float4 hv = *reinterpret_cast<const float4*>(hrow + k);
        const float4 wv = *reinterpret_cast<const float4*>(Wfc + k);
        s += hv.x * wv.x + hv.y * wv.y + hv.z * wv.z + hv.w * wv.w;
    }
#pragma unroll
    for (int o = 16; o; o >>= 1) s += __shfl_xor_sync(0xFFFFFFFFu, s, o);
    if (lane == 0) ys[(size_t)b * L_ + t] = s + bfc[0];
}

// ---------------------------------------------------------------------------
// Setup kernels
// ---------------------------------------------------------------------------
__global__ void expand_weights_kernel(const float* __restrict__ Wih1,
                                      const float* __restrict__ Whh1,
                                      const float* __restrict__ Wih2,
                                      const float* __restrict__ Whh2)
{
    const int n = blockIdx.x;
    const int k = threadIdx.x;
    const float* src;
    __half* dst;
    switch (blockIdx.y) {
        case 0:  src = Wih1; dst = g_Wih1e; break;
        case 1:  src = Whh1; dst = g_Whh1e; break;
        case 2:  src = Wih2; dst = g_Wih2e; break;
        default: src = Whh2; dst = g_Whh2e; break;
    }
    const float v = src[n * 512 + k];
    const __half hi = __float2half(v);
    dst[(size_t)n * KP + k]       = hi;    // W = [Whi | Whi]
    dst[(size_t)n * KP + 512 + k] = hi;
}

__global__ void build_axp_kernel(const float* __restrict__ x)
{
    const int m = blockIdx.x;       // t*512 + b
    const int t = m >> 9;
    const int b = m & 511;
    const int k = threadIdx.x;
    const float v = x[(size_t)b * XW + t + k];
    const __half hi = __float2half(v);
    const __half lo = __float2half(v - __half2float(hi));
    __half* row = g_Axp + (size_t)m * KP;
    row[k]       = hi;
    row[512 + k] = lo;
}

__global__ void init_h_kernel(const float* __restrict__ h1in,
                              const float* __restrict__ h2in)
{
    const int b = blockIdx.x;
    const int j = threadIdx.x;
    const float v1 = h1in[b * H_ + j];
    const float v2 = h2in[b * H_ + j];
    g_h1[b * H_ + j] = v1;
    g_h2[b * H_ + j] = v2;
    const __half h1hi = __float2half(v1);
    const __half h1lo = __float2half(v1 - __half2float(h1hi));
    const __half h2hi = __float2half(v2);
    const __half h2lo = __float2half(v2 - __half2float(h2hi));
    g_h1e[(size_t)b * KP + j]       = h1hi;
    g_h1e[(size_t)b * KP + 512 + j] = h1lo;
    g_h2e[(size_t)b * KP + j]       = h2hi;
    g_h2e[(size_t)b * KP + 512 + j] = h2lo;
}

// ---------------------------------------------------------------------------
extern "C" void kernel_launch(void* const* d_in, const int* in_sizes, int n_in,
                              void* d_out, int out_size)
{
    const float* x     = (const float*)d_in[0];
    const float* h1_in = (const float*)d_in[1];
    const float* h2_in = (const float*)d_in[2];
    const float* W_ih1 = (const float*)d_in[3];
    const float* W_hh1 = (const float*)d_in[4];
    const float* b_ih1 = (const float*)d_in[5];
    const float* b_hh1 = (const float*)d_in[6];
    const float* W_ih2 = (const float*)d_in[7];
    const float* W_hh2 = (const float*)d_in[8];
    const float* b_ih2 = (const float*)d_in[9];
    const float* b_hh2 = (const float*)d_in[10];
    const float* W_fc  = (const float*)d_in[11];
    const float* b_fc  = (const float*)d_in[12];

    float* out = (float*)d_out;     // [B*L ys][B*H h1][B*H h2]

    cudaFuncSetAttribute(gemm_phase1, cudaFuncAttributeMaxDynamicSharedMemorySize, SMEM_P1);
    cudaFuncSetAttribute(gemm_step,   cudaFuncAttributeMaxDynamicSharedMemorySize, SMEM_STEP);

    // Setup
    expand_weights_kernel<<<dim3(G3, 4), 512>>>(W_ih1, W_hh1, W_ih2, W_hh2);
    init_h_kernel<<<B_, 512>>>(h1_in, h2_in);
    build_axp_kernel<<<L_ * B_, 512>>>(x);

    // Phase 1: all layer-1 input projections + initial GH1 (merged grid)
    gemm_phase1<<<dim3(12, 260), 256, SMEM_P1>>>(b_ih1, b_hh1);

    // Recurrent scan: 2 launches per step
    for (int t = 0; t < L_; t++) {
        ew_step<<<B_, 128>>>(t);
        gemm_step<<<dim3(12, 4, 3), 256, SMEM_STEP>>>(b_hh1, b_ih2, b_hh2);
    }

    // Final ew2 + hidden-state writeback, then all y outputs in one pass
    final_kernel<<<B_, 512>>>(out);
    y_all_kernel<<<dim3(L_, 64), 256>>>(W_fc, b_fc, out);
}

// round 15
// speedup vs baseline: 1.0080x; 1.0080x over previous
#include <cuda_runtime.h>
#include <cuda_fp16.h>
#include <cstdint>
#include <cstddef>

// ---------------------------------------------------------------------------
// Problem constants
// ---------------------------------------------------------------------------
#define B_  512
#define L_  64
#define H_  512
#define G3  1536            // 3*H
#define XW  575             // T + L - 1
#define KP  1024            // expanded K: [hi(512) | lo(512)] (fp16 split, A side)
#define BM  128
#define BN  128
#define BKC 64              // fp16 K per chunk
#define NCH (KP / BKC)      // 16
#define APAD_B 144          // padded smem row stride in bytes (64*2 + 16)
#define TILE_BYTES (BM * APAD_B)        // 18432
#define SMEM_P1   (4 * TILE_BYTES)      // phase-1: 2-stage x (A,W) = 73728
#define SMEM_SCAN (10 * TILE_BYTES)     // scan: 8 W chunks + 2 A stages = 184320
#define NCTA 144

// ---------------------------------------------------------------------------
// Scratch (device globals; allocation is forbidden)
// ---------------------------------------------------------------------------
__device__ __align__(16) float g_GI1[(size_t)L_ * B_ * G3];
__device__ __align__(16) float g_GH1[B_ * G3];
__device__ __align__(16) float g_GI2[B_ * G3];
__device__ __align__(16) float g_GH2[B_ * G3];
__device__ __align__(16) float g_h1[B_ * H_];
__device__ __align__(16) float g_h2[B_ * H_];
__device__ __align__(16) float g_h2hist[(size_t)L_ * B_ * H_];   // h2 after each step

__device__ __align__(16) __half g_h1e[B_ * KP];                // [hi|lo]
__device__ __align__(16) __half g_h2e[B_ * KP];
__device__ __align__(16) __half g_Axp[(size_t)L_ * B_ * KP];   // x windows [hi|lo]
__device__ __align__(16) __half g_Wih1e[(size_t)G3 * KP];      // [Whi|Whi]
__device__ __align__(16) __half g_Whh1e[(size_t)G3 * KP];
__device__ __align__(16) __half g_Wih2e[(size_t)G3 * KP];
__device__ __align__(16) __half g_Whh2e[(size_t)G3 * KP];

__device__ unsigned long long g_bar = 0ULL;   // monotonic grid-barrier counter

// ---------------------------------------------------------------------------
// Helpers
// ---------------------------------------------------------------------------
__device__ __forceinline__ uint32_t s2u(const void* p) {
    return (uint32_t)__cvta_generic_to_shared(p);
}
__device__ __forceinline__ void cpa16(uint32_t dst, const void* src) {
    asm volatile("cp.async.cg.shared.global [%0], [%1], 16;" :: "r"(dst), "l"(src));
}
__device__ __forceinline__ void cpa_commit() {
    asm volatile("cp.async.commit_group;" ::: "memory");
}
template <int N> __device__ __forceinline__ void cpa_wait() {
    asm volatile("cp.async.wait_group %0;" :: "n"(N) : "memory");
}
__device__ __forceinline__ void ldsm4(uint32_t& r0, uint32_t& r1, uint32_t& r2,
                                      uint32_t& r3, uint32_t addr) {
    asm volatile("ldmatrix.sync.aligned.m8n8.x4.shared.b16 {%0,%1,%2,%3}, [%4];"
                 : "=r"(r0), "=r"(r1), "=r"(r2), "=r"(r3) : "r"(addr));
}
__device__ __forceinline__ void mma16816(float* d, const uint32_t* a,
                                         uint32_t b0, uint32_t b1) {
    asm volatile(
        "mma.sync.aligned.m16n8k16.row.col.f32.f16.f16.f32 "
        "{%0,%1,%2,%3}, {%4,%5,%6,%7}, {%8,%9}, {%0,%1,%2,%3};"
        : "+f"(d[0]), "+f"(d[1]), "+f"(d[2]), "+f"(d[3])
        : "r"(a[0]), "r"(a[1]), "r"(a[2]), "r"(a[3]), "r"(b0), "r"(b1));
}
__device__ __forceinline__ float sigf(float v) { return 1.f / (1.f + __expf(-v)); }

union Pack4 { __half h[4]; uint2 u; };

// ---------------------------------------------------------------------------
// Pair-tile loader (phase-1): A tile + W tile [128 x 64] fp16, padded rows.
// ---------------------------------------------------------------------------
__device__ __forceinline__ void load_tile(const __half* __restrict__ A,
                                          const __half* __restrict__ W,
                                          int m0, int n0, int kc,
                                          uint32_t sA, uint32_t sW, int tid)
{
#pragma unroll
    for (int i = 0; i < 4; i++) {
        const int g  = tid + i * 256;
        const int r  = g >> 3;
        const int cg = g & 7;
        const uint32_t so = (uint32_t)(r * APAD_B + cg * 16);
        cpa16(sA + so, A + (size_t)(m0 + r) * KP + kc * BKC + cg * 8);
        cpa16(sW + so, W + (size_t)(n0 + r) * KP + kc * BKC + cg * 8);
    }
    cpa_commit();
}

// Single-tensor chunk loader (scan A chunks)
__device__ __forceinline__ void load_A(const __half* __restrict__ A,
                                       int m0, int kc, uint32_t sA, int tid)
{
#pragma unroll
    for (int i = 0; i < 4; i++) {
        const int g  = tid + i * 256;
        const int r  = g >> 3;
        const int cg = g & 7;
        cpa16(sA + (uint32_t)(r * APAD_B + cg * 16),
              A + (size_t)(m0 + r) * KP + kc * BKC + cg * 8);
    }
    cpa_commit();
}

// ---------------------------------------------------------------------------
// Phase-1 GEMM core (2-stage pair pipeline) — unchanged from R12/R13.
// ---------------------------------------------------------------------------
__device__ __forceinline__ void gemm_core_p1(const __half* __restrict__ A,
                                             const __half* __restrict__ W,
                                             const float* __restrict__ bias,
                                             float* __restrict__ C,
                                             int m0, int n0, char* smem, int tid)
{
    const int warp = tid >> 5;
    const int lane = tid & 31;
    const int wm   = warp >> 2;
    const int wn   = warp & 3;

    const uint32_t sb  = s2u(smem);
    const uint32_t sA0 = sb;
    const uint32_t sW0 = sb + TILE_BYTES;
    const uint32_t sA1 = sb + 2 * TILE_BYTES;
    const uint32_t sW1 = sb + 3 * TILE_BYTES;

    const uint32_t aoff = (uint32_t)((wm * 64 + (lane & 15)) * APAD_B + (lane >> 4) * 16);
    const int bg = lane >> 3;
    const uint32_t boff = (uint32_t)((wn * 32 + ((bg >> 1) * 8) + (lane & 7)) * APAD_B
                                     + (bg & 1) * 16);

    float acc[4][4][4];
#pragma unroll
    for (int i = 0; i < 4; i++)
#pragma unroll
        for (int j = 0; j < 4; j++)
#pragma unroll
            for (int e = 0; e < 4; e++) acc[i][j][e] = 0.f;

    load_tile(A, W, m0, n0, 0, sA0, sW0, tid);

#pragma unroll 1
    for (int c = 0; c < NCH; c++) {
        const uint32_t bufA = (c & 1) ? sA1 : sA0;
        const uint32_t bufW = (c & 1) ? sW1 : sW0;
        if (c + 1 < NCH) {
            load_tile(A, W, m0, n0, c + 1, (c & 1) ? sA0 : sA1, (c & 1) ? sW0 : sW1, tid);
            cpa_wait<1>();
        } else {
            cpa_wait<0>();
        }
        __syncthreads();

#pragma unroll
        for (int ks = 0; ks < 4; ks++) {
            uint32_t a[4][4];
            uint32_t b[8];
#pragma unroll
            for (int mi = 0; mi < 4; mi++)
                ldsm4(a[mi][0], a[mi][1], a[mi][2], a[mi][3],
                      bufA + aoff + mi * (16 * APAD_B) + ks * 32);
            ldsm4(b[0], b[1], b[2], b[3], bufW + boff + ks * 32);
            ldsm4(b[4], b[5], b[6], b[7], bufW + boff + 16 * APAD_B + ks * 32);
#pragma unroll
            for (int mi = 0; mi < 4; mi++)
#pragma unroll
                for (int nj = 0; nj < 4; nj++)
                    mma16816(acc[mi][nj], a[mi], b[nj * 2], b[nj * 2 + 1]);
        }
        __syncthreads();
    }

    const int r    = lane >> 2;
    const int cpos = (lane & 3) * 2;
#pragma unroll
    for (int mi = 0; mi < 4; mi++) {
        const int m = m0 + wm * 64 + mi * 16 + r;
        float* row0 = C + (size_t)m * G3;
        float* row1 = C + (size_t)(m + 8) * G3;
#pragma unroll
        for (int nj = 0; nj < 4; nj++) {
            const int n = n0 + wn * 32 + nj * 8 + cpos;
            const float bx = bias[n];
            const float by = bias[n + 1];
            *reinterpret_cast<float2*>(row0 + n) =
                make_float2(acc[mi][nj][0] + bx, acc[mi][nj][1] + by);
            *reinterpret_cast<float2*>(row1 + n) =
                make_float2(acc[mi][nj][2] + bx, acc[mi][nj][3] + by);
        }
    }
}

__global__ void __launch_bounds__(256, 2) gemm_phase1(const float* __restrict__ b_ih1,
                                                      const float* __restrict__ b_hh1)
{
    extern __shared__ __align__(128) char smem[];
    const int by = blockIdx.y;
    if (by < 256) {
        gemm_core_p1(g_Axp, g_Wih1e, b_ih1, g_GI1,
                     by * BM, blockIdx.x * BN, smem, threadIdx.x);
    } else {
        gemm_core_p1(g_h1e, g_Whh1e, b_hh1, g_GH1,
                     (by - 256) * BM, blockIdx.x * BN, smem, threadIdx.x);
    }
}

// ---------------------------------------------------------------------------
// GRU elementwise for one row (warp-collective, 16 cols/lane).
// kind 1: layer-1 (reads GI1[t], GH1, h1; writes h1, h1e)
// kind 2: layer-2 (reads GI2, GH2, h2; writes h2, h2e, h2hist[t])
// ---------------------------------------------------------------------------
__device__ __forceinline__ void ew_row(int kind, int b, int t, int lane)
{
    const float* gi;
    const float* gh;
    float* hst;
    __half* he;
    if (kind == 1) {
        gi = g_GI1 + ((size_t)t * B_ + b) * G3;
        gh = g_GH1 + (size_t)b * G3;
        hst = g_h1 + (size_t)b * H_;
        he = g_h1e + (size_t)b * KP;
    } else {
        gi = g_GI2 + (size_t)b * G3;
        gh = g_GH2 + (size_t)b * G3;
        hst = g_h2 + (size_t)b * H_;
        he = g_h2e + (size_t)b * KP;
    }
#pragma unroll
    for (int jj = 0; jj < 4; jj++) {
        const int j = lane * 4 + jj * 128;
        const float4 gir = *reinterpret_cast<const float4*>(gi + j);
        const float4 giz = *reinterpret_cast<const float4*>(gi + H_ + j);
        const float4 gin = *reinterpret_cast<const float4*>(gi + 2 * H_ + j);
        const float4 ghr = *reinterpret_cast<const float4*>(gh + j);
        const float4 ghz = *reinterpret_cast<const float4*>(gh + H_ + j);
        const float4 ghn = *reinterpret_cast<const float4*>(gh + 2 * H_ + j);
        const float4 hp  = *reinterpret_cast<const float4*>(hst + j);

        const float gir_[4] = {gir.x, gir.y, gir.z, gir.w};
        const float giz_[4] = {giz.x, giz.y, giz.z, giz.w};
        const float gin_[4] = {gin.x, gin.y, gin.z, gin.w};
        const float ghr_[4] = {ghr.x, ghr.y, ghr.z, ghr.w};
        const float ghz_[4] = {ghz.x, ghz.y, ghz.z, ghz.w};
        const float ghn_[4] = {ghn.x, ghn.y, ghn.z, ghn.w};
        const float hp_[4]  = {hp.x, hp.y, hp.z, hp.w};

        float hv[4];
#pragma unroll
        for (int e = 0; e < 4; e++) {
            const float r = sigf(gir_[e] + ghr_[e]);
            const float z = sigf(giz_[e] + ghz_[e]);
            const float n = tanhf(gin_[e] + r * ghn_[e]);
            hv[e] = (1.f - z) * n + z * hp_[e];
        }
        *reinterpret_cast<float4*>(hst + j) = make_float4(hv[0], hv[1], hv[2], hv[3]);
        if (kind == 2)
            *reinterpret_cast<float4*>(g_h2hist + ((size_t)t * B_ + b) * H_ + j) =
                make_float4(hv[0], hv[1], hv[2], hv[3]);

        Pack4 phi, plo;
#pragma unroll
        for (int e = 0; e < 4; e++) {
            phi.h[e] = __float2half(hv[e]);
            plo.h[e] = __float2half(hv[e] - __half2float(phi.h[e]));
        }
        *reinterpret_cast<uint2*>(he + j)       = phi.u;
        *reinterpret_cast<uint2*>(he + 512 + j) = plo.u;
    }
}

// ---------------------------------------------------------------------------
// Persistent scan kernel: grid 144 x 256.  Weight tile resident in smem.
// Per step: ew phase -> grid barrier -> GEMM phase -> grid barrier.
// ---------------------------------------------------------------------------
__global__ void __launch_bounds__(256, 1) scan_kernel(const float* __restrict__ b_hh1,
                                                      const float* __restrict__ b_ih2,
                                                      const float* __restrict__ b_hh2)
{
    extern __shared__ __align__(128) char smem[];
    const int tid  = threadIdx.x;
    const int flat = blockIdx.x;              // 0..143
    const int xq   = flat % 12;
    const int yq   = (flat / 12) % 4;
    const int zq   = flat / 48;
    const int n0   = xq * BN;
    const int m0   = yq * BM;

    const __half* Aten;
    const __half* Wten;
    const float* bias;
    float* Cten;
    switch (zq) {
        case 0:  Aten = g_h1e; Wten = g_Wih2e; bias = b_ih2; Cten = g_GI2; break;
        case 1:  Aten = g_h2e; Wten = g_Whh2e; bias = b_hh2; Cten = g_GH2; break;
        default: Aten = g_h1e; Wten = g_Whh1e; bias = b_hh1; Cten = g_GH1; break;
    }

    const uint32_t sb = s2u(smem);
    const uint32_t sW = sb;                         // 8 chunks resident
    const uint32_t sA = sb + 8 * TILE_BYTES;        // 2 A stages

    // One-time: load resident W tile (hi half only: k < 512, chunks 0..7)
#pragma unroll 1
    for (int kc = 0; kc < 8; kc++) {
#pragma unroll
        for (int i = 0; i < 4; i++) {
            const int g  = tid + i * 256;
            const int r  = g >> 3;
            const int cg = g & 7;
            cpa16(sW + (uint32_t)(kc * TILE_BYTES + r * APAD_B + cg * 16),
                  Wten + (size_t)(n0 + r) * KP + kc * BKC + cg * 8);
        }
        cpa_commit();
    }
    cpa_wait<0>();
    __syncthreads();

    const int warp = tid >> 5;
    const int lane = tid & 31;
    const int wm   = warp >> 2;
    const int wn   = warp & 3;
    const uint32_t aoff = (uint32_t)((wm * 64 + (lane & 15)) * APAD_B + (lane >> 4) * 16);
    const int bg = lane >> 3;
    const uint32_t boff = (uint32_t)((wn * 32 + ((bg >> 1) * 8) + (lane & 7)) * APAD_B
                                     + (bg & 1) * 16);
    const int gw = flat * 8 + warp;               // 0..1151

#pragma unroll 1
    for (int t = 0; t < L_; t++) {
        // ---- ew phase: one row per warp ----
        if (t > 0 && gw < 512)            ew_row(2, gw, t - 1, lane);
        if (gw >= 512 && gw < 1024)       ew_row(1, gw - 512, t, lane);

        // ---- grid barrier ----
        __syncthreads();
        if (tid == 0) {
            __threadfence();
            const unsigned long long t0 = atomicAdd(&g_bar, 1ULL);
            const unsigned long long goal =
                t0 - (t0 % (unsigned long long)NCTA) + (unsigned long long)NCTA;
            while (*(volatile unsigned long long*)&g_bar < goal) __nanosleep(64);
            __threadfence();   // reader-side: invalidate L1 before GEMM/next-phase loads
        }
        __syncthreads();

        // ---- GEMM phase (skip the useless GH1(L) tile at the last step) ----
        if (!(t == L_ - 1 && zq == 2)) {
            float acc[4][4][4];
#pragma unroll
            for (int i = 0; i < 4; i++)
#pragma unroll
                for (int j = 0; j < 4; j++)
#pragma unroll
                    for (int e = 0; e < 4; e++) acc[i][j][e] = 0.f;

            load_A(Aten, m0, 0, sA, tid);

#pragma unroll 1
            for (int c = 0; c < NCH; c++) {
                const uint32_t bufA = sA + (uint32_t)((c & 1) * TILE_BYTES);
                if (c + 1 < NCH) {
                    load_A(Aten, m0, c + 1, sA + (uint32_t)(((c + 1) & 1) * TILE_BYTES), tid);
                    cpa_wait<1>();
                } else {
                    cpa_wait<0>();
                }
                __syncthreads();

                const uint32_t bufW = sW + (uint32_t)((c & 7) * TILE_BYTES);
#pragma unroll
                for (int ks = 0; ks < 4; ks++) {
                    uint32_t a[4][4];
                    uint32_t b[8];
#pragma unroll
                    for (int mi = 0; mi < 4; mi++)
                        ldsm4(a[mi][0], a[mi][1], a[mi][2], a[mi][3],
                              bufA + aoff + mi * (16 * APAD_B) + ks * 32);
                    ldsm4(b[0], b[1], b[2], b[3], bufW + boff + ks * 32);
                    ldsm4(b[4], b[5], b[6], b[7], bufW + boff + 16 * APAD_B + ks * 32);
#pragma unroll
                    for (int mi = 0; mi < 4; mi++)
#pragma unroll
                        for (int nj = 0; nj < 4; nj++)
                            mma16816(acc[mi][nj], a[mi], b[nj * 2], b[nj * 2 + 1]);
                }
                __syncthreads();
            }

            // Epilogue
            const int r    = lane >> 2;
            const int cpos = (lane & 3) * 2;
#pragma unroll
            for (int mi = 0; mi < 4; mi++) {
                const int m = m0 + wm * 64 + mi * 16 + r;
                float* row0 = Cten + (size_t)m * G3;
                float* row1 = Cten + (size_t)(m + 8) * G3;
#pragma unroll
                for (int nj = 0; nj < 4; nj++) {
                    const int n = n0 + wn * 32 + nj * 8 + cpos;
                    const float bx = bias[n];
                    const float by = bias[n + 1];
                    *reinterpret_cast<float2*>(row0 + n) =
                        make_float2(acc[mi][nj][0] + bx, acc[mi][nj][1] + by);
                    *reinterpret_cast<float2*>(row1 + n) =
                        make_float2(acc[mi][nj][2] + bx, acc[mi][nj][3] + by);
                }
            }
        }

        // ---- grid barrier ----
        __syncthreads();
        if (tid == 0) {
            __threadfence();
            const unsigned long long t0 = atomicAdd(&g_bar, 1ULL);
            const unsigned long long goal =
                t0 - (t0 % (unsigned long long)NCTA) + (unsigned long long)NCTA;
            while (*(volatile unsigned long long*)&g_bar < goal) __nanosleep(64);
            __threadfence();
        }
        __syncthreads();
    }
}

// ---------------------------------------------------------------------------
// Final elementwise: ew2(L-1) + write final h1/h2 + h2hist[L-1].
// ---------------------------------------------------------------------------
__global__ void final_kernel(float* __restrict__ out)
{
    const int b = blockIdx.x;
    const int j = threadIdx.x;
    const float* gi = g_GI2 + (size_t)b * G3;
    const float* gh = g_GH2 + (size_t)b * G3;
    const float r = sigf(gi[j] + gh[j]);
    const float z = sigf(gi[H_ + j] + gh[H_ + j]);
    const float n = tanhf(gi[2 * H_ + j] + r * gh[2 * H_ + j]);
    const float h = (1.f - z) * n + z * g_h2[b * H_ + j];

    g_h2hist[((size_t)(L_ - 1) * B_ + b) * H_ + j] = h;
    out[B_ * L_ + b * H_ + j]           = g_h1[b * H_ + j];   // final h1
    out[B_ * L_ + B_ * H_ + b * H_ + j] = h;                  // final h2
}

// ---------------------------------------------------------------------------
// y_all: ys[b, t] = h2hist[t, b, :] . Wfc + bfc.  grid (L, 64), 256 thr.
// ---------------------------------------------------------------------------
__global__ void y_all_kernel(const float* __restrict__ Wfc,
                             const float* __restrict__ bfc,
                             float* __restrict__ ys)
{
    const int t    = blockIdx.x;
    const int b    = blockIdx.y * 8 + (threadIdx.x >> 5);
    const int lane = threadIdx.x & 31;
    const float* hrow = g_h2hist + ((size_t)t * B_ + b) * H_;
    float s = 0.f;
#pragma unroll
    for (int i = 0; i < 4; i++) {
        const int k = i * 128 + lane * 4;
        const float4 hv = *reinterpret_cast<const float4*>(hrow + k);
        const float4 wv = *reinterpret_cast<const float4*>(Wfc + k);
        s += hv.x * wv.x + hv.y * wv.y + hv.z * wv.z + hv.w * wv.w;
    }
#pragma unroll
    for (int o = 16; o; o >>= 1) s += __shfl_xor_sync(0xFFFFFFFFu, s, o);
    if (lane == 0) ys[(size_t)b * L_ + t] = s + bfc[0];
}

// ---------------------------------------------------------------------------
// Setup kernels
// ---------------------------------------------------------------------------
__global__ void expand_weights_kernel(const float* __restrict__ Wih1,
                                      const float* __restrict__ Whh1,
                                      const float* __restrict__ Wih2,
                                      const float* __restrict__ Whh2)
{
    const int n = blockIdx.x;
    const int k = threadIdx.x;
    const float* src;
    __half* dst;
    switch (blockIdx.y) {
        case 0:  src = Wih1; dst = g_Wih1e; break;
        case 1:  src = Whh1; dst = g_Whh1e; break;
        case 2:  src = Wih2; dst = g_Wih2e; break;
        default: src = Whh2; dst = g_Whh2e; break;
    }
    const float v = src[n * 512 + k];
    const __half hi = __float2half(v);
    dst[(size_t)n * KP + k]       = hi;    // W = [Whi | Whi]
    dst[(size_t)n * KP + 512 + k] = hi;
}

__global__ void build_axp_kernel(const float* __restrict__ x)
{
    const int m = blockIdx.x;       // t*512 + b
    const int t = m >> 9;
    const int b = m & 511;
    const int k = threadIdx.x;
    const float v = x[(size_t)b * XW + t + k];
    const __half hi = __float2half(v);
    const __half lo = __float2half(v - __half2float(hi));
    __half* row = g_Axp + (size_t)m * KP;
    row[k]       = hi;
    row[512 + k] = lo;
}

__global__ void init_h_kernel(const float* __restrict__ h1in,
                              const float* __restrict__ h2in)
{
    const int b = blockIdx.x;
    const int j = threadIdx.x;
    const float v1 = h1in[b * H_ + j];
    const float v2 = h2in[b * H_ + j];
    g_h1[b * H_ + j] = v1;
    g_h2[b * H_ + j] = v2;
    const __half h1hi = __float2half(v1);
    const __half h1lo = __float2half(v1 - __half2float(h1hi));
    const __half h2hi = __float2half(v2);
    const __half h2lo = __float2half(v2 - __half2float(h2hi));
    g_h1e[(size_t)b * KP + j]       = h1hi;
    g_h1e[(size_t)b * KP + 512 + j] = h1lo;
    g_h2e[(size_t)b * KP + j]       = h2hi;
    g_h2e[(size_t)b * KP + 512 + j] = h2lo;
}

// ---------------------------------------------------------------------------
extern "C" void kernel_launch(void* const* d_in, const int* in_sizes, int n_in,
                              void* d_out, int out_size)
{
    const float* x     = (const float*)d_in[0];
    const float* h1_in = (const float*)d_in[1];
    const float* h2_in = (const float*)d_in[2];
    const float* W_ih1 = (const float*)d_in[3];
    const float* W_hh1 = (const float*)d_in[4];
    const float* b_ih1 = (const float*)d_in[5];
    const float* b_hh1 = (const float*)d_in[6];
    const float* W_ih2 = (const float*)d_in[7];
    const float* W_hh2 = (const float*)d_in[8];
    const float* b_ih2 = (const float*)d_in[9];
    const float* b_hh2 = (const float*)d_in[10];
    const float* W_fc  = (const float*)d_in[11];
    const float* b_fc  = (const float*)d_in[12];

    float* out = (float*)d_out;     // [B*L ys][B*H h1][B*H h2]

    cudaFuncSetAttribute(gemm_phase1, cudaFuncAttributeMaxDynamicSharedMemorySize, SMEM_P1);
    cudaFuncSetAttribute(scan_kernel, cudaFuncAttributeMaxDynamicSharedMemorySize, SMEM_SCAN);

    // Setup
    expand_weights_kernel<<<dim3(G3, 4), 512>>>(W_ih1, W_hh1, W_ih2, W_hh2);
    init_h_kernel<<<B_, 512>>>(h1_in, h2_in);
    build_axp_kernel<<<L_ * B_, 512>>>(x);

    // Phase 1: all layer-1 input projections + initial GH1 (merged grid)
    gemm_phase1<<<dim3(12, 260), 256, SMEM_P1>>>(b_ih1, b_hh1);

    // Persistent recurrent scan: ONE launch for all 64 steps
    scan_kernel<<<NCTA, 256, SMEM_SCAN>>>(b_hh1, b_ih2, b_hh2);

    // Final ew2 + hidden-state writeback, then all y outputs in one pass
    final_kernel<<<B_, 512>>>(out);
    y_all_kernel<<<dim3(L_, 64), 256>>>(W_fc, b_fc, out);
}